// round 12
// baseline (speedup 1.0000x reference)
#include <cuda_runtime.h>
#include <math_constants.h>

// Problem shape (fixed): B=32, H=16, N=1024, D=128, fp32.
// IDENTITY: softmax is shift-invariant per (b,h) => attn depends only on
// dot(t[n], w2). transformer_t_1 / w1 / concat_b are never read.
//
// Persistent fused kernel, 128 blocks x 512 threads, 4 bh per block,
// SOFTWARE-PIPELINED: pass2(bh i) and pass1(bh i+1) run in ONE merged
// barrier-free streaming loop (double-buffered smem scores). Keeps the
// L2 re-read window at 128 concurrent bh (~77 MB < 126 MB L2).
#define Bc 32
#define Hc 16
#define Nc 1024
#define Dc 128
#define D4 (Dc / 4)                 // 32 float4 per row
#define NBH (Bc * Hc)               // 512
#define NBLK 128
#define BH_PER_BLK 4
#define NTH 512

__global__ __launch_bounds__(NTH, 1)
void fused_kernel(const float* __restrict__ t,
                  const int*   __restrict__ padding,
                  const float* __restrict__ w,      // [256]: w1 | w2
                  float*       __restrict__ out)
{
    __shared__ float s_buf[2][Nc];     // double buffer: scores -> factor
    __shared__ float s_red[16];
    __shared__ int   s_padd;

    const int tid  = threadIdx.x;
    const int wid  = tid >> 5;
    const int lane = tid & 31;
    const int g    = lane >> 3;
    const int sub  = lane & 7;

    const float4* wf = reinterpret_cast<const float4*>(w);
    const float4 u0 = wf[D4 + sub];
    const float4 u1 = wf[D4 + sub + 8];
    const float4 u2 = wf[D4 + sub + 16];
    const float4 u3 = wf[D4 + sub + 24];

    const int bh0 = blockIdx.x * BH_PER_BLK;
    const float4* tb[BH_PER_BLK];
    #pragma unroll
    for (int i = 0; i < BH_PER_BLK; i++)
        tb[i] = reinterpret_cast<const float4*>(t) + (size_t)(bh0 + i) * Nc * D4;

    if (tid == 0) s_padd = Nc;

    // ================= pass1(bh0): scores into s_buf[0] =================
    {
        float* s_sc = s_buf[0];
        #pragma unroll 2
        for (int it = 0; it < 16; it++) {
            const int row = it * 64 + wid * 4 + g;
            const float4* trow = tb[0] + row * D4;
            float4 c0 = trow[sub];
            float4 c1 = trow[sub + 8];
            float4 c2 = trow[sub + 16];
            float4 c3 = trow[sub + 24];
            float sc = c0.x*u0.x + c0.y*u0.y + c0.z*u0.z + c0.w*u0.w
                     + c1.x*u1.x + c1.y*u1.y + c1.z*u1.z + c1.w*u1.w
                     + c2.x*u2.x + c2.y*u2.y + c2.z*u2.z + c2.w*u2.w
                     + c3.x*u3.x + c3.y*u3.y + c3.z*u3.z + c3.w*u3.w;
            sc += __shfl_xor_sync(0xffffffffu, sc, 1);
            sc += __shfl_xor_sync(0xffffffffu, sc, 2);
            sc += __shfl_xor_sync(0xffffffffu, sc, 4);
            if (sub == 0) s_sc[row] = sc;
        }
    }
    __syncthreads();   // s_buf[0] + s_padd init complete

    // softmax + pipeline: i = bh being finalized/scaled, scores of i in buf[i&1]
    #pragma unroll 1
    for (int i = 0; i < BH_PER_BLK; i++) {
        float* s_sc = s_buf[i & 1];

        // -------- softmax on s_sc (entry: synced, s_padd == Nc) --------
        {
            const int* pb = padding + ((bh0 + i) >> 4) * Nc;   // b = bh / Hc
            int local = Nc;
            #pragma unroll
            for (int n = tid; n < Nc; n += NTH)
                if (pb[n] == 0) local = min(local, n);
            if (local < Nc) atomicMin(&s_padd, local);
        }
        __syncthreads();                                        // [A]
        const int padd = s_padd;

        float m = -CUDART_INF_F;
        #pragma unroll
        for (int n = tid; n < Nc; n += NTH)
            if (n < padd) m = fmaxf(m, s_sc[n]);
        #pragma unroll
        for (int o = 16; o > 0; o >>= 1)
            m = fmaxf(m, __shfl_xor_sync(0xffffffffu, m, o));
        if (lane == 0) s_red[wid] = m;
        __syncthreads();                                        // [B]
        float mx = -CUDART_INF_F;
        #pragma unroll
        for (int k = 0; k < 16; k++) mx = fmaxf(mx, s_red[k]);
        if (tid == 0) s_padd = Nc;          // reset for next bh (read done)
        __syncthreads();                                        // [C]

        float esum = 0.f;
        #pragma unroll
        for (int n = tid; n < Nc; n += NTH) {
            float e = (n < padd) ? __expf(s_sc[n] - mx) : 0.f;
            s_sc[n] = e;
            esum += e;
        }
        #pragma unroll
        for (int o = 16; o > 0; o >>= 1)
            esum += __shfl_xor_sync(0xffffffffu, esum, o);
        if (lane == 0) s_red[wid] = esum;
        __syncthreads();                                        // [D]
        float tot = 0.f;
        #pragma unroll
        for (int k = 0; k < 16; k++) tot += s_red[k];
        const float inv = (tot > 0.f) ? (1.f / tot) : 0.f;
        #pragma unroll
        for (int n = tid; n < Nc; n += NTH)
            s_sc[n] = fmaf(s_sc[n], inv, 1.f);   // factor = attn + 1
        __syncthreads();                                        // [E]

        float4* ob = reinterpret_cast<float4*>(out) + (size_t)(bh0 + i) * Nc * D4;

        if (i < BH_PER_BLK - 1) {
            // ---- MERGED: scale bh i (4 f4/thread/iter, L2 hits)
            //      + scores of bh i+1 (4 f4/thread/iter, DRAM). No barriers.
            float* s_nx = s_buf[(i + 1) & 1];
            const float4* tnx = tb[i + 1];
            #pragma unroll 1
            for (int it = 0; it < 16; it++) {
                // pass1 (next bh): quad-per-warp
                const int row = it * 64 + wid * 4 + g;
                const float4* trow = tnx + row * D4;
                float4 c0 = trow[sub];
                float4 c1 = trow[sub + 8];
                float4 c2 = trow[sub + 16];
                float4 c3 = trow[sub + 24];
                // pass2 (current bh): 4 float4/thread covering 2048 f4/iter
                const int j = it * 2048 + tid;
                float4 x0 = __ldcs(tb[i] + j);
                float4 x1 = __ldcs(tb[i] + j + 512);
                float4 x2 = __ldcs(tb[i] + j + 1024);
                float4 x3 = __ldcs(tb[i] + j + 1536);

                float sc = c0.x*u0.x + c0.y*u0.y + c0.z*u0.z + c0.w*u0.w
                         + c1.x*u1.x + c1.y*u1.y + c1.z*u1.z + c1.w*u1.w
                         + c2.x*u2.x + c2.y*u2.y + c2.z*u2.z + c2.w*u2.w
                         + c3.x*u3.x + c3.y*u3.y + c3.z*u3.z + c3.w*u3.w;
                sc += __shfl_xor_sync(0xffffffffu, sc, 1);
                sc += __shfl_xor_sync(0xffffffffu, sc, 2);
                sc += __shfl_xor_sync(0xffffffffu, sc, 4);
                if (sub == 0) s_nx[row] = sc;

                float f0 = s_sc[(j)        >> 5];   // warp-uniform broadcast
                float f1 = s_sc[(j + 512)  >> 5];
                float f2 = s_sc[(j + 1024) >> 5];
                float f3 = s_sc[(j + 1536) >> 5];
                x0.x *= f0; x0.y *= f0; x0.z *= f0; x0.w *= f0;
                x1.x *= f1; x1.y *= f1; x1.z *= f1; x1.w *= f1;
                x2.x *= f2; x2.y *= f2; x2.z *= f2; x2.w *= f2;
                x3.x *= f3; x3.y *= f3; x3.z *= f3; x3.w *= f3;
                __stcs(ob + j,        x0);
                __stcs(ob + j + 512,  x1);
                __stcs(ob + j + 1024, x2);
                __stcs(ob + j + 1536, x3);
            }
            __syncthreads();   // s_nx complete for next softmax
        } else {
            // ---- final: scale bh 3 only, ILP 4 ----
            #pragma unroll 2
            for (int j = tid; j < Nc * D4; j += NTH * 4) {
                float4 x0 = __ldcs(tb[i] + j);
                float4 x1 = __ldcs(tb[i] + j + NTH);
                float4 x2 = __ldcs(tb[i] + j + NTH * 2);
                float4 x3 = __ldcs(tb[i] + j + NTH * 3);
                float f0 = s_sc[(j)           >> 5];
                float f1 = s_sc[(j + NTH)     >> 5];
                float f2 = s_sc[(j + NTH * 2) >> 5];
                float f3 = s_sc[(j + NTH * 3) >> 5];
                x0.x *= f0; x0.y *= f0; x0.z *= f0; x0.w *= f0;
                x1.x *= f1; x1.y *= f1; x1.z *= f1; x1.w *= f1;
                x2.x *= f2; x2.y *= f2; x2.z *= f2; x2.w *= f2;
                x3.x *= f3; x3.y *= f3; x3.z *= f3; x3.w *= f3;
                __stcs(ob + j,           x0);
                __stcs(ob + j + NTH,     x1);
                __stcs(ob + j + NTH * 2, x2);
                __stcs(ob + j + NTH * 3, x3);
            }
        }
    }
}

extern "C" void kernel_launch(void* const* d_in, const int* in_sizes, int n_in,
                              void* d_out, int out_size)
{
    const float* t       = (const float*)d_in[1];
    const int*   padding = (const int*)d_in[2];

    const float* w = nullptr;
    for (int i = 3; i < n_in; i++)
        if (in_sizes[i] == 2 * Dc) { w = (const float*)d_in[i]; }

    fused_kernel<<<NBLK, NTH>>>(t, padding, w, (float*)d_out);
    (void)out_size;
}

// round 13
// speedup vs baseline: 1.0953x; 1.0953x over previous
#include <cuda_runtime.h>
#include <math_constants.h>
#include <float.h>

// Problem shape (fixed): B=32, H=16, N=1024, D=128, fp32.
// IDENTITY: softmax is shift-invariant per (b,h) => attn depends only on
// dot(t[n], w2). transformer_t_1 / w1 / concat_b are never read.
//
// Persistent fused kernel: 128 blocks x 512 threads, 4 bh per block,
// SEQUENTIAL pass1 -> online-softmax -> pass2 per bh (this ordering keeps the
// L2 re-read window at ~128 MB; R12 proved interleaving breaks it).
// Softmax uses a single-pass online reduction: 4 barriers/bh, no full sweeps.
// Dataset guarantee: lengths in [N/2, N] => padd >= 512 => n = tid (<512)
// is always valid, so per-thread max is always finite.
#define Bc 32
#define Hc 16
#define Nc 1024
#define Dc 128
#define D4 (Dc / 4)                 // 32 float4 per row
#define NBH (Bc * Hc)               // 512
#define NBLK 128
#define BH_PER_BLK 4
#define NTH 512

__global__ __launch_bounds__(NTH, 1)
void fused_kernel(const float* __restrict__ t,
                  const int*   __restrict__ padding,
                  const float* __restrict__ w,      // [256]: w1 | w2
                  float*       __restrict__ out)
{
    __shared__ float  s_sc[Nc];        // raw scores -> factor (in place)
    __shared__ float2 s_ms[16];        // per-warp (max, sum)
    __shared__ int    s_pd[16];        // per-warp padd min

    const int tid  = threadIdx.x;
    const int wid  = tid >> 5;
    const int lane = tid & 31;
    const int g    = lane >> 3;
    const int sub  = lane & 7;

    const float4* wf = reinterpret_cast<const float4*>(w);
    const float4 u0 = wf[D4 + sub];
    const float4 u1 = wf[D4 + sub + 8];
    const float4 u2 = wf[D4 + sub + 16];
    const float4 u3 = wf[D4 + sub + 24];

    const int bh0 = blockIdx.x * BH_PER_BLK;

    #pragma unroll 1
    for (int i = 0; i < BH_PER_BLK; i++) {
        const int bh = bh0 + i;
        const float4* tb = reinterpret_cast<const float4*>(t) + (size_t)bh * Nc * D4;

        // ---------------- pass 1: raw scores -> s_sc ----------------
        #pragma unroll 2
        for (int it = 0; it < 16; it++) {
            const int row = it * 64 + wid * 4 + g;
            const float4* trow = tb + row * D4;
            float4 c0 = trow[sub];
            float4 c1 = trow[sub + 8];
            float4 c2 = trow[sub + 16];
            float4 c3 = trow[sub + 24];
            float sc = c0.x*u0.x + c0.y*u0.y + c0.z*u0.z + c0.w*u0.w
                     + c1.x*u1.x + c1.y*u1.y + c1.z*u1.z + c1.w*u1.w
                     + c2.x*u2.x + c2.y*u2.y + c2.z*u2.z + c2.w*u2.w
                     + c3.x*u3.x + c3.y*u3.y + c3.z*u3.z + c3.w*u3.w;
            sc += __shfl_xor_sync(0xffffffffu, sc, 1);
            sc += __shfl_xor_sync(0xffffffffu, sc, 2);
            sc += __shfl_xor_sync(0xffffffffu, sc, 4);
            if (sub == 0) s_sc[row] = sc;
        }

        // padd: thread-local min over n = tid, tid+512 (no shared atomics)
        {
            const int* pb = padding + (bh >> 4) * Nc;   // b = bh / Hc
            int local = Nc;
            if (pb[tid] == 0)       local = tid;
            if (pb[tid + 512] == 0) local = min(local, tid + 512);
            #pragma unroll
            for (int o = 16; o > 0; o >>= 1)
                local = min(local, __shfl_xor_sync(0xffffffffu, local, o));
            if (lane == 0) s_pd[wid] = local;
        }
        __syncthreads();                               // [B1] s_sc, s_pd ready

        int padd = Nc;
        #pragma unroll
        for (int k = 0; k < 16; k++) padd = min(padd, s_pd[k]);

        // ----- online (max,sum): each thread owns n = tid and tid+512 -----
        {
            float v0 = s_sc[tid];                      // always valid (padd>=512)
            float v1 = s_sc[tid + 512];
            bool  ok1 = (tid + 512) < padd;
            float m = ok1 ? fmaxf(v0, v1) : v0;
            float sum = __expf(v0 - m) + (ok1 ? __expf(v1 - m) : 0.f);
            #pragma unroll
            for (int o = 16; o > 0; o >>= 1) {
                float m2 = __shfl_xor_sync(0xffffffffu, m, o);
                float s2 = __shfl_xor_sync(0xffffffffu, sum, o);
                float nm = fmaxf(m, m2);
                sum = sum * __expf(m - nm) + s2 * __expf(m2 - nm);
                m = nm;
            }
            if (lane == 0) s_ms[wid] = make_float2(m, sum);
        }
        __syncthreads();                               // [B2]

        float mx = -FLT_MAX;
        #pragma unroll
        for (int k = 0; k < 16; k++) mx = fmaxf(mx, s_ms[k].x);
        float tot = 0.f;
        #pragma unroll
        for (int k = 0; k < 16; k++)
            tot += s_ms[k].y * __expf(s_ms[k].x - mx);
        const float inv = (tot > 0.f) ? (1.f / tot) : 0.f;

        // factor in place (each thread overwrites only its own 2 entries)
        {
            float v0 = s_sc[tid];
            float v1 = s_sc[tid + 512];
            float f0 = fmaf(__expf(v0 - mx), inv, 1.f);
            float f1 = ((tid + 512) < padd) ? fmaf(__expf(v1 - mx), inv, 1.f) : 1.f;
            s_sc[tid]       = f0;
            s_sc[tid + 512] = f1;
        }
        __syncthreads();                               // [B3] factor ready

        // ---------------- pass 2: scale (L2 hits), ILP 4 ----------------
        float4* ob = reinterpret_cast<float4*>(out) + (size_t)bh * Nc * D4;
        #pragma unroll 2
        for (int j = tid; j < Nc * D4; j += NTH * 4) {
            float4 x0 = __ldcs(tb + j);
            float4 x1 = __ldcs(tb + j + NTH);
            float4 x2 = __ldcs(tb + j + NTH * 2);
            float4 x3 = __ldcs(tb + j + NTH * 3);
            float f0 = s_sc[(j)           >> 5];       // warp-uniform LDS
            float f1 = s_sc[(j + NTH)     >> 5];
            float f2 = s_sc[(j + NTH * 2) >> 5];
            float f3 = s_sc[(j + NTH * 3) >> 5];
            x0.x *= f0; x0.y *= f0; x0.z *= f0; x0.w *= f0;
            x1.x *= f1; x1.y *= f1; x1.z *= f1; x1.w *= f1;
            x2.x *= f2; x2.y *= f2; x2.z *= f2; x2.w *= f2;
            x3.x *= f3; x3.y *= f3; x3.z *= f3; x3.w *= f3;
            __stcs(ob + j,           x0);
            __stcs(ob + j + NTH,     x1);
            __stcs(ob + j + NTH * 2, x2);
            __stcs(ob + j + NTH * 3, x3);
        }
        __syncthreads();                               // [B4] protect s_sc
    }
}

extern "C" void kernel_launch(void* const* d_in, const int* in_sizes, int n_in,
                              void* d_out, int out_size)
{
    const float* t       = (const float*)d_in[1];
    const int*   padding = (const int*)d_in[2];

    const float* w = nullptr;
    for (int i = 3; i < n_in; i++)
        if (in_sizes[i] == 2 * Dc) { w = (const float*)d_in[i]; }

    fused_kernel<<<NBLK, NTH>>>(t, padding, w, (float*)d_out);
    (void)out_size;
}